// round 13
// baseline (speedup 1.0000x reference)
#include <cuda_runtime.h>
#include <cstdint>

#define N   2048
#define KM  192
#define NB  16
#define T   512
#define RPB (N/NB)          // 128 rows per block
#define NW  (T/32)          // 16 warps
#define TXB (NB * (RPB*4 + 4))   // 8256 bytes expected per mbarrier phase

// ---------------- device state (no allocations allowed) ----------------
__device__ float g_V[2][N*KM];     // ping-pong basis, row-major stride KM
__device__ int   g_cols[KM];
__device__ int   g_k;
__device__ int   g_kk;
__device__ unsigned g_kl0, g_kl1;  // k_loop key

// ---------------- smem / cluster helpers ----------------
__device__ __forceinline__ unsigned smem_u32(const void* p) {
    return (unsigned)__cvta_generic_to_shared(p);
}
__device__ __forceinline__ unsigned mapa_rank(unsigned addr, unsigned rank) {
    unsigned r;
    asm("mapa.shared::cluster.u32 %0, %1, %2;" : "=r"(r) : "r"(addr), "r"(rank));
    return r;
}
// remote smem store whose completion is tracked on the REMOTE mbarrier
__device__ __forceinline__ void st_async_f32(unsigned raddr, float v, unsigned rmbar) {
    asm volatile(
        "st.async.shared::cluster.mbarrier::complete_tx::bytes.b32 [%0], %1, [%2];"
        :: "r"(raddr), "r"(__float_as_uint(v)), "r"(rmbar) : "memory");
}
__device__ __forceinline__ void mbar_init(unsigned addr, unsigned cnt) {
    asm volatile("mbarrier.init.shared.b64 [%0], %1;" :: "r"(addr), "r"(cnt) : "memory");
}
__device__ __forceinline__ void mbar_expect(unsigned addr, unsigned tx) {
    asm volatile("mbarrier.arrive.expect_tx.shared.b64 _, [%0], %1;"
                 :: "r"(addr), "r"(tx) : "memory");
}
__device__ __forceinline__ void mbar_wait(unsigned addr, unsigned parity) {
    asm volatile(
        "{\n\t.reg .pred P;\n\t"
        "WL_%=:\n\t"
        "mbarrier.try_wait.parity.acquire.cta.shared::cta.b64 P, [%0], %1, 0x989680;\n\t"
        "@P bra.uni WD_%=;\n\t"
        "bra.uni WL_%=;\n\t"
        "WD_%=:\n\t}"
        :: "r"(addr), "r"(parity) : "memory");
}
#define CLUSTER_SYNC() do { \
    asm volatile("barrier.cluster.arrive.aligned;" ::: "memory"); \
    asm volatile("barrier.cluster.wait.aligned;"   ::: "memory"); \
} while (0)

// ---------------- threefry2x32 block (exact JAX rotation schedule) ----------------
__device__ __forceinline__ void tf2x32(unsigned k0, unsigned k1,
                                       unsigned c0, unsigned c1,
                                       unsigned &o0, unsigned &o1) {
    unsigned ks2 = k0 ^ k1 ^ 0x1BD11BDAu;
    unsigned x0 = c0 + k0, x1 = c1 + k1;
#define RR(r) { x0 += x1; x1 = (x1 << (r)) | (x1 >> (32 - (r))); x1 ^= x0; }
    RR(13) RR(15) RR(26) RR(6)   x0 += k1;  x1 += ks2 + 1u;
    RR(17) RR(29) RR(16) RR(24)  x0 += ks2; x1 += k0 + 2u;
    RR(13) RR(15) RR(26) RR(6)   x0 += k0;  x1 += k1 + 3u;
    RR(17) RR(29) RR(16) RR(24)  x0 += k1;  x1 += ks2 + 4u;
    RR(13) RR(15) RR(26) RR(6)   x0 += ks2; x1 += k0 + 5u;
#undef RR
    o0 = x0; o1 = x1;
}
__device__ __forceinline__ unsigned tf_bits32(unsigned k0, unsigned k1, unsigned i) {
    unsigned a, b;
    tf2x32(k0, k1, 0u, i, a, b);
    return a ^ b;
}
__device__ __forceinline__ float u01(unsigned b) {
    return __uint_as_float((b >> 9) | 0x3f800000u) - 1.0f;
}

__global__ void __launch_bounds__(T, 1)
dpp_kernel(const float* __restrict__ e, const float* __restrict__ v,
           const int* __restrict__ seedp, float* __restrict__ out) {
    const int tid = threadIdx.x, bid = blockIdx.x;
    const int lane = tid & 31, wid = tid >> 5;

    __shared__ __align__(16) float sp[2][N];      // p replicas (pushed by all blocks)
    __shared__ float sbs[2][NB];                  // block sums  (pushed by all blocks)
    __shared__ __align__(8) unsigned long long mbar_store[2];
    __shared__ __align__(16) float sa[KM];
    __shared__ int   s_cols[KM];
    __shared__ float swred[NW];
    __shared__ int   s_item;
    __shared__ float s_n2;
    __shared__ unsigned s_k0, s_k1;
    __shared__ unsigned char sf[N];
    __shared__ int   sc[T];

    const unsigned mb0 = smem_u32(&mbar_store[0]);
    const unsigned mb1 = smem_u32(&mbar_store[1]);

    // ---------------- init: mbarriers (per-launch smem => replay-safe) ----------
    if (tid == 0) {
        mbar_init(mb0, 1);
        mbar_init(mb1, 1);
        mbar_expect(mb0, TXB);   // first use: initial gather publish, consumed i=0
        mbar_expect(mb1, TXB);   // first use: end of i=0, consumed i=1
    }
    if (tid < RPB) out[bid * RPB + tid] = 0.0f;

    // ---------------- phase 0 (block 0): PRNG thinning + column compaction ------
    if (bid == 0) {
        if (tid == 0) {
            // jax.random.key(seed)=(0,seed); partitionable split: key_i = block(key,(0,i))
            unsigned key0 = 0u, key1 = (unsigned)seedp[0];
            unsigned a0, b0, a1, b1;
            tf2x32(key0, key1, 0u, 0u, a0, b0);   // k_idx
            tf2x32(key0, key1, 0u, 1u, a1, b1);   // k_loop
            s_k0 = a0; s_k1 = b0;
            g_kl0 = a1; g_kl1 = b1;
        }
        __syncthreads();
        unsigned kk0 = s_k0, kk1 = s_k1;
        for (int pp = tid; pp < N; pp += T) {
            float ev = e[pp];
            float thr = __fdiv_rn(ev, __fadd_rn(ev, 1.0f));
            sf[pp] = (u01(tf_bits32(kk0, kk1, (unsigned)pp)) < thr) ? 1 : 0;
        }
        __syncthreads();
        int base4 = tid * 4, cnt = 0;
        #pragma unroll
        for (int j = 0; j < 4; j++) cnt += sf[base4 + j];
        sc[tid] = cnt; __syncthreads();
        for (int off = 1; off < T; off <<= 1) {
            int val = sc[tid];
            int add = (tid >= off) ? sc[tid - off] : 0;
            __syncthreads();
            sc[tid] = val + add;
            __syncthreads();
        }
        int excl = sc[tid] - cnt, total = sc[T - 1];
        int pos = excl;
        for (int j = 0; j < 4; j++) {
            if (sf[base4 + j]) { if (pos < KM) g_cols[pos] = base4 + j; pos++; }
        }
        if (tid == 0) { g_k = total; g_kk = total < KM ? total : KM; }
    }

    CLUSTER_SYNC();   // mbarrier inits + g_cols/g_kk/g_kl* visible cluster-wide

    const int kk = g_kk;
    const int kfull = g_k;
    const unsigned kl0 = g_kl0, kl1 = g_kl1;

    for (int j = tid; j < KM; j += T) s_cols[j] = (j < kk) ? g_cols[j] : 0;
    __syncthreads();

    // ---------------- phase 1: gather V0 (4 threads/row) + p + DSMEM push -------
    {
        int pr = tid >> 2, h = tid & 3;
        int r = bid * RPB + pr;
        const float* vr = v + (size_t)r * N;
        float* Vr = g_V[0] + (size_t)r * KM;
        float acc = 0.f;
        for (int j = h; j < kk; j += 4) {
            float x = vr[s_cols[j]];
            Vr[j] = x;
            acc = fmaf(x, x, acc);
        }
        float accT = acc;
        accT += __shfl_xor_sync(0xFFFFFFFFu, accT, 1);
        accT += __shfl_xor_sync(0xFFFFFFFFu, accT, 2);
        if (h == 0) {
            unsigned pa = smem_u32(&sp[0][r]);
            #pragma unroll
            for (unsigned rk = 0; rk < NB; rk++)
                st_async_f32(mapa_rank(pa, rk), accT, mapa_rank(mb0, rk));
        }
        float val = acc;
        #pragma unroll
        for (int o = 16; o; o >>= 1) val += __shfl_down_sync(0xFFFFFFFFu, val, o);
        if (lane == 0) swred[wid] = val;
    }
    __syncthreads();
    if (wid == 0) {
        float s = (lane < NW) ? swred[lane] : 0.f;
        #pragma unroll
        for (int o = 16; o; o >>= 1) s += __shfl_xor_sync(0xFFFFFFFFu, s, o);
        if (lane < NB) {
            unsigned ba = smem_u32(&sbs[0][bid]);
            st_async_f32(mapa_rank(ba, (unsigned)lane), s, mapa_rank(mb0, (unsigned)lane));
        }
    }

    // ---------------- main loop: local mbarrier wait + all-local selection ------
    for (int i = 0; i < kk; i++) {
        const int m = kk - i;
        const int par = i & 1;
        const unsigned mbc = par ? mb1 : mb0;

        mbar_wait(mbc, (unsigned)((i >> 1) & 1));   // data for iter i is local now
        if (tid == 0) mbar_expect(mbc, TXB);        // re-arm for use at i+2

        if (wid == 0) {
            // u_i = uniform(fold_in(k_loop, i))
            unsigned f0, f1, w0, w1;
            tf2x32(kl0, kl1, 0u, (unsigned)i, f0, f1);
            tf2x32(f0, f1, 0u, 0u, w0, w1);
            const float u = u01(w0 ^ w1);

            // 16-lane scan of local block sums
            float sb = (lane < NB) ? sbs[par][lane] : 0.f;
            float incl = sb;
            #pragma unroll
            for (int o = 1; o < 16; o <<= 1) {
                float nv = __shfl_up_sync(0xFFFFFFFFu, incl, o);
                if (lane >= o) incl += nv;
            }
            const float S = __shfl_sync(0xFFFFFFFFu, incl, 15);
            const float thr = u * S;

            unsigned bmB = __ballot_sync(0xFFFFFFFFu, (lane < NB) && incl > thr) & 0xFFFFu;
            int item; float n2;
            if (bmB == 0u) {
                item = 0;                               // argmax(all-False) -> 0
                n2 = sp[par][0];
            } else {
                int bstar = __ffs(bmB) - 1;
                float bexcl = __shfl_sync(0xFFFFFFFFu, incl - sb, bstar);
                float4 pv = ((const float4*)&sp[par][bstar * RPB])[lane];   // LDS128
                float ls = (pv.x + pv.y) + (pv.z + pv.w);
                float incl2 = ls;
                #pragma unroll
                for (int o = 1; o < 32; o <<= 1) {
                    float nv = __shfl_up_sync(0xFFFFFFFFu, incl2, o);
                    if (lane >= o) incl2 += nv;
                }
                float run = bexcl + (incl2 - ls);
                int c = 0x7FFFFFFF; float cn = 0.f;
                float qq[4] = {pv.x, pv.y, pv.z, pv.w};
                #pragma unroll
                for (int j = 0; j < 4; j++) {
                    run += qq[j];
                    if (c == 0x7FFFFFFF && run > thr) { c = lane * 4 + j; cn = qq[j]; }
                }
                unsigned bm2 = __ballot_sync(0xFFFFFFFFu, c != 0x7FFFFFFF);
                if (bm2) {
                    int l2 = __ffs(bm2) - 1;
                    item = bstar * RPB + __shfl_sync(0xFFFFFFFFu, c, l2);
                    n2   = __shfl_sync(0xFFFFFFFFu, cn, l2);
                } else {                                 // fp boundary fallback
                    item = bstar * RPB + RPB - 1;
                    n2   = __shfl_sync(0xFFFFFFFFu, pv.w, 31);
                }
            }
            if (lane == 0) {
                s_item = item; s_n2 = n2;
                if (bid == 0) out[item] = 1.0f;
            }
        }
        __syncthreads();
        const int item = s_item;

        if (m == 1) continue;   // reference keeps V unchanged when m==1; no publish

        // ---- a-row pull from owner's g_V region (one L2 RT) ----
        const float* arow = g_V[par] + (size_t)item * KM;
        if (tid < KM / 4) ((float4*)sa)[tid] = __ldcg((const float4*)arow + tid);
        __syncthreads();
        const float n2  = s_n2;                          // == ||a||^2
        const float al  = sa[m - 1];
        const float nrm = sqrtf(n2);
        const float sh  = (al >= 0.f) ? nrm : -nrm;
        const float den = fmaf(fabsf(al), nrm, n2);      // ||u||^2 / 2
        const float tau = (den > 0.f) ? (1.0f / den) : 0.f;

        // ---- Householder sweep, 4 threads/row + DSMEM push of new p ----
        {
            int pr = tid >> 2, h = tid & 3;
            int r = bid * RPB + pr;
            const float* vc = g_V[par] + (size_t)r * KM;
            float* vn = g_V[par ^ 1] + (size_t)r * KM;
            float t0 = 0.f, t1 = 0.f;
            int j = h;
            for (; j + 4 < m; j += 8) {
                t0 = fmaf(vc[j],     sa[j],     t0);
                t1 = fmaf(vc[j + 4], sa[j + 4], t1);
            }
            for (; j < m; j += 4) t0 = fmaf(vc[j], sa[j], t0);
            float t = t0 + t1;
            t += __shfl_xor_sync(0xFFFFFFFFu, t, 1);
            t += __shfl_xor_sync(0xFFFFFFFFu, t, 2);
            float w = tau * fmaf(sh, vc[m - 1], t);
            float acc = 0.f;
            for (j = h; j < m - 1; j += 4) {
                float x = fmaf(-w, sa[j], vc[j]);
                vn[j] = x;
                acc = fmaf(x, x, acc);
            }
            float accT = acc;
            accT += __shfl_xor_sync(0xFFFFFFFFu, accT, 1);
            accT += __shfl_xor_sync(0xFFFFFFFFu, accT, 2);
            if (h == 0) {
                unsigned pa = smem_u32(&sp[par ^ 1][r]);
                unsigned mbn = (par ^ 1) ? mb1 : mb0;
                #pragma unroll
                for (unsigned rk = 0; rk < NB; rk++)
                    st_async_f32(mapa_rank(pa, rk), accT, mapa_rank(mbn, rk));
            }
            float val = acc;
            #pragma unroll
            for (int o = 16; o; o >>= 1) val += __shfl_down_sync(0xFFFFFFFFu, val, o);
            if (lane == 0) swred[wid] = val;
        }
        __syncthreads();
        if (wid == 0) {
            float s = (lane < NW) ? swred[lane] : 0.f;
            #pragma unroll
            for (int o = 16; o; o >>= 1) s += __shfl_xor_sync(0xFFFFFFFFu, s, o);
            if (lane < NB) {
                unsigned ba = smem_u32(&sbs[par ^ 1][bid]);
                unsigned mbn = (par ^ 1) ? mb1 : mb0;
                st_async_f32(mapa_rank(ba, (unsigned)lane), s,
                             mapa_rank(mbn, (unsigned)lane));
            }
        }
    }

    // k == n -> all ones
    if (kfull == N) {
        if (tid < RPB) out[bid * RPB + tid] = 1.0f;
    }

    CLUSTER_SYNC();   // no CTA exits while peers' st.async may target its smem
}

extern "C" void kernel_launch(void* const* d_in, const int* in_sizes, int n_in,
                              void* d_out, int out_size) {
    const float* e    = (const float*)d_in[0];
    const float* v    = (const float*)d_in[1];
    const int*   seed = (const int*)d_in[2];
    float*       o    = (float*)d_out;
    (void)in_sizes; (void)n_in; (void)out_size;

    cudaFuncSetAttribute(dpp_kernel,
                         cudaFuncAttributeNonPortableClusterSizeAllowed, 1);

    cudaLaunchConfig_t cfg = {};
    cfg.gridDim  = dim3(NB, 1, 1);
    cfg.blockDim = dim3(T, 1, 1);
    cfg.dynamicSmemBytes = 0;
    cfg.stream = 0;
    cudaLaunchAttribute attrs[1];
    attrs[0].id = cudaLaunchAttributeClusterDimension;
    attrs[0].val.clusterDim.x = NB;
    attrs[0].val.clusterDim.y = 1;
    attrs[0].val.clusterDim.z = 1;
    cfg.attrs = attrs;
    cfg.numAttrs = 1;

    cudaLaunchKernelEx(&cfg, dpp_kernel, e, v, seed, o);
}